// round 7
// baseline (speedup 1.0000x reference)
#include <cuda_runtime.h>
#include <cuda_fp16.h>

#define IMG      384
#define W_OUT    48          // 8 * 48 = 384 exact
#define LCOLS    60          // 48 + 6+6 halo
#define TILE_H   64          // output rows per block
#define ROWS_PT  32          // rows per vertical slice (threadIdx.y in {0,1})
#define GRP      208         // 12 pixels * 16B + 16B pad
#define ROW_B    1088        // row stride bytes: 272 words ≡ 16 (mod 32)
#define SMEM_BYTES (TILE_H * ROW_B)   // 69632 B -> 3 blocks/SM

// Normalized 1D gaussian, sigma=2, ws=13 (literals -> FFMA-imm form)
__device__ constexpr float GW[13] = {
    0.0022181959f, 0.0087731350f, 0.0270231560f, 0.0648251852f,
    0.1211093910f, 0.1762131227f, 0.1996756275f, 0.1762131227f,
    0.1211093910f, 0.0648251852f, 0.0270231560f, 0.0087731350f,
    0.0022181959f };

__device__ __forceinline__ float4 f4z() { return make_float4(0.f, 0.f, 0.f, 0.f); }

union H2U { __half2 h; unsigned u; };

// Vertical slice: 13-tap ring over 44 input rows -> 32 output rows to smem (fp16).
// SAFE: all 44 rows and the column are in-bounds -> raw unpredicated LDG.
template<bool SAFE>
__device__ __forceinline__ void vpass(const float4* __restrict__ cb, char* srow,
                                      int r0, int gw, bool wok)
{
    float4 win[13];
    #pragma unroll
    for (int i = 0; i < 12; ++i) {
        const int h = r0 + i;
        if (SAFE)
            win[i] = __ldg(cb + ((size_t)h * IMG + gw) * 4);
        else
            win[i] = (wok && (unsigned)h < (unsigned)IMG)
                   ? __ldg(cb + ((size_t)h * IMG + gw) * 4) : f4z();
    }
    #pragma unroll
    for (int r = 0; r < ROWS_PT; ++r) {
        const int h = r0 + 12 + r;
        if (SAFE)
            win[(r + 12) % 13] = __ldg(cb + ((size_t)h * IMG + gw) * 4);
        else
            win[(r + 12) % 13] = (wok && (unsigned)h < (unsigned)IMG)
                   ? __ldg(cb + ((size_t)h * IMG + gw) * 4) : f4z();
        float4 a = f4z();
        #pragma unroll
        for (int k = 0; k < 13; ++k) {
            const float4 v = win[(r + k) % 13];
            const float wk = GW[k];          // literal -> FFMA-imm
            a.x = fmaf(wk, v.x, a.x);
            a.y = fmaf(wk, v.y, a.y);
            a.z = fmaf(wk, v.z, a.z);
            a.w = fmaf(wk, v.w, a.w);
        }
        H2U u0, u1;
        u0.h = __floats2half2_rn(a.x, a.y);
        u1.h = __floats2half2_rn(a.z, a.w);
        uint2 pk; pk.x = u0.u; pk.y = u1.u;
        *reinterpret_cast<uint2*>(srow + r * ROW_B) = pk;
    }
}

__global__ __launch_bounds__(256, 3)
void gauss13_kernel(const float* __restrict__ in, float* __restrict__ out)
{
    extern __shared__ char smem[];   // [TILE_H rows][5 groups of 12 px + pads]

    const int z  = blockIdx.z;
    const int n  = z >> 1;
    const int p  = z & 1;            // channel half (ch 0-7 / 8-15)
    const int x0 = blockIdx.x * W_OUT;
    const int y0 = blockIdx.y * TILE_H;

    const float4* __restrict__ ibase =
        reinterpret_cast<const float4*>(in) + (size_t)n * (IMG * IMG * 4) + p * 2;
    float4* __restrict__ obase =
        reinterpret_cast<float4*>(out) + (size_t)n * (IMG * IMG * 4) + p * 2;

    // ---------------- vertical pass (global -> smem fp16) ----------------
    {
        const int tx  = threadIdx.x;      // 0..127
        const int col = tx >> 1;          // 0..63; 0..59 active
        const int cq  = tx & 1;
        if (col < LCOLS) {
            const int gw  = x0 - 6 + col;
            const bool wok = ((unsigned)gw < (unsigned)IMG);
            const int r0  = y0 + (int)threadIdx.y * ROWS_PT - 6;
            const float4* cb = ibase + cq;
            // smem byte offset for this (col, cq) within a row
            char* srow = smem + ((int)threadIdx.y * ROWS_PT) * ROW_B
                       + (col / 12) * GRP + (col % 12) * 16 + cq * 8;
            const bool safe = wok && (r0 >= 0) && (r0 + ROWS_PT + 11 < IMG);
            if (safe) vpass<true >(cb, srow, r0, gw, true);
            else      vpass<false>(cb, srow, r0, gw, wok);
        }
    }
    __syncthreads();

    // ---------------- horizontal pass (smem fp16 -> global f32), chunked --------
    {
        const int tid = (int)threadIdx.y * 128 + (int)threadIdx.x;  // 0..255
        const int cq  = tid & 1;
        const int ch  = (tid >> 1) & 3;    // chunk: outputs pixels 12ch..12ch+11
        const int row = tid >> 3;          // 0..31 (two passes: row, row+32)

        #pragma unroll
        for (int pass = 0; pass < 2; ++pass) {
            const int r = row + pass * 32;
            const char* rowbase = smem + r * ROW_B + ch * GRP + cq * 8;

            float4 acc[12];
            #pragma unroll
            for (int o = 0; o < 12; ++o) acc[o] = f4z();

            #pragma unroll
            for (int j = 0; j < 24; ++j) {     // inputs: pixels 12ch + j
                const int off = j * 16 + ((j >= 12) ? 16 : 0);   // skip group pad
                uint2 pk = *reinterpret_cast<const uint2*>(rowbase + off);
                H2U u0, u1; u0.u = pk.x; u1.u = pk.y;
                float2 f01 = __half22float2(u0.h);
                float2 f23 = __half22float2(u1.h);
                #pragma unroll
                for (int o = 0; o < 12; ++o) {
                    const int k = j - o;       // tap index
                    if (k >= 0 && k < 13) {    // compile-time pruned
                        const float wk = GW[k];
                        acc[o].x = fmaf(wk, f01.x, acc[o].x);
                        acc[o].y = fmaf(wk, f01.y, acc[o].y);
                        acc[o].z = fmaf(wk, f23.x, acc[o].z);
                        acc[o].w = fmaf(wk, f23.y, acc[o].w);
                    }
                }
            }

            const int gy = y0 + r;
            float4* ob = obase + cq;
            #pragma unroll
            for (int o = 0; o < 12; ++o) {
                const int gx = x0 + 12 * ch + o;   // always < 384
                ob[((size_t)gy * IMG + gx) * 4] = acc[o];
            }
        }
    }
}

extern "C" void kernel_launch(void* const* d_in, const int* in_sizes, int n_in,
                              void* d_out, int out_size)
{
    (void)in_sizes; (void)n_in; (void)out_size;
    const float* x = (const float*)d_in[0];
    float* y = (float*)d_out;

    cudaFuncSetAttribute(gauss13_kernel,
                         cudaFuncAttributeMaxDynamicSharedMemorySize, SMEM_BYTES);

    dim3 grid(IMG / W_OUT /* 8 */, IMG / TILE_H /* 6 */, 32 * 2);
    dim3 block(128, 2);
    gauss13_kernel<<<grid, block, SMEM_BYTES>>>(x, y);
}

// round 8
// speedup vs baseline: 1.4127x; 1.4127x over previous
#include <cuda_runtime.h>
#include <cuda_fp16.h>

#define IMG      384
#define W_OUT    48          // 8 * 48 = 384 exact
#define LCOLS    60          // 48 + 6+6 halo
#define TILE_H   32          // output rows per block
#define ROWS_PT  16          // rows per vertical slice (threadIdx.y in {0,1})
#define GRP      208         // 12 pixels * 16B + 16B pad
#define ROW_B    1088        // 5*GRP=1040, padded; 272 words ≡ 16 (mod 32)
#define SMEM_BYTES (TILE_H * ROW_B)   // 34816 B -> 3 blocks/SM

// Normalized 1D gaussian, sigma=2, ws=13 (literals -> FFMA-imm form)
__device__ constexpr float GW[13] = {
    0.0022181959f, 0.0087731350f, 0.0270231560f, 0.0648251852f,
    0.1211093910f, 0.1762131227f, 0.1996756275f, 0.1762131227f,
    0.1211093910f, 0.0648251852f, 0.0270231560f, 0.0087731350f,
    0.0022181959f };

__device__ __forceinline__ float4 f4z() { return make_float4(0.f, 0.f, 0.f, 0.f); }

union H2U { __half2 h; unsigned u; };

__global__ __launch_bounds__(256, 3)
void gauss13_kernel(const float* __restrict__ in, float* __restrict__ out)
{
    extern __shared__ char smem[];   // [TILE_H rows][5 groups of (12 px + pad)]

    const int z  = blockIdx.z;
    const int n  = z >> 1;
    const int p  = z & 1;            // channel half (ch 0-7 / 8-15)
    const int x0 = blockIdx.x * W_OUT;
    const int y0 = blockIdx.y * TILE_H;

    const float4* __restrict__ ibase =
        reinterpret_cast<const float4*>(in) + (size_t)n * (IMG * IMG * 4) + p * 2;
    float4* __restrict__ obase =
        reinterpret_cast<float4*>(out) + (size_t)n * (IMG * IMG * 4) + p * 2;

    // ---------------- vertical pass (global -> smem fp16), register ring ----------------
    {
        const int tx  = threadIdx.x;      // 0..127
        const int col = tx >> 1;          // 0..63; only 0..59 active
        const int cq  = tx & 1;
        if (col < LCOLS) {
            const int gw  = x0 - 6 + col;
            const bool wok = ((unsigned)gw < (unsigned)IMG);
            const int r0  = y0 + (int)threadIdx.y * ROWS_PT - 6;
            const float4* cb = ibase + cq;
            char* sp = smem + ((int)threadIdx.y * ROWS_PT) * ROW_B
                     + (col / 12) * GRP + (col % 12) * 16 + cq * 8;

            float4 win[13];
            #pragma unroll
            for (int i = 0; i < 12; ++i) {
                int h = r0 + i;
                win[i] = (wok && (unsigned)h < (unsigned)IMG)
                       ? __ldg(cb + ((size_t)h * IMG + gw) * 4) : f4z();
            }
            #pragma unroll
            for (int r = 0; r < ROWS_PT; ++r) {
                int h = r0 + 12 + r;
                win[(r + 12) % 13] = (wok && (unsigned)h < (unsigned)IMG)
                       ? __ldg(cb + ((size_t)h * IMG + gw) * 4) : f4z();
                float4 a = f4z();
                #pragma unroll
                for (int k = 0; k < 13; ++k) {
                    const float4 v = win[(r + k) % 13];
                    const float wk = GW[k];      // literal -> FFMA-imm
                    a.x = fmaf(wk, v.x, a.x);
                    a.y = fmaf(wk, v.y, a.y);
                    a.z = fmaf(wk, v.z, a.z);
                    a.w = fmaf(wk, v.w, a.w);
                }
                H2U u0, u1;
                u0.h = __floats2half2_rn(a.x, a.y);
                u1.h = __floats2half2_rn(a.z, a.w);
                uint2 pk; pk.x = u0.u; pk.y = u1.u;
                *reinterpret_cast<uint2*>(sp + r * ROW_B) = pk;
            }
        }
    }
    __syncthreads();

    // ---------------- horizontal pass (smem fp16 -> global f32), chunked ---------------
    {
        const int tid = (int)threadIdx.y * 128 + (int)threadIdx.x;  // 0..255
        const int cq  = tid & 1;
        const int ch  = (tid >> 1) & 3;    // chunk: output pixels 12ch .. 12ch+11
        const int row = tid >> 3;          // 0..31

        const char* rowbase = smem + row * ROW_B + ch * GRP + cq * 8;

        float4 acc[12];
        #pragma unroll
        for (int o = 0; o < 12; ++o) acc[o] = f4z();

        #pragma unroll
        for (int j = 0; j < 24; ++j) {     // input pixels 12ch + j (halo-shifted)
            const int off = j * 16 + ((j >= 12) ? 16 : 0);   // skip group pad
            uint2 pk = *reinterpret_cast<const uint2*>(rowbase + off);
            H2U u0, u1; u0.u = pk.x; u1.u = pk.y;
            float2 f01 = __half22float2(u0.h);
            float2 f23 = __half22float2(u1.h);
            #pragma unroll
            for (int o = 0; o < 12; ++o) {
                const int k = j - o;       // tap index into GW
                if (k >= 0 && k < 13) {    // compile-time pruned
                    const float wk = GW[k];
                    acc[o].x = fmaf(wk, f01.x, acc[o].x);
                    acc[o].y = fmaf(wk, f01.y, acc[o].y);
                    acc[o].z = fmaf(wk, f23.x, acc[o].z);
                    acc[o].w = fmaf(wk, f23.y, acc[o].w);
                }
            }
        }

        const int gy = y0 + row;
        float4* ob = obase + cq;
        #pragma unroll
        for (int o = 0; o < 12; ++o) {
            const int gx = x0 + 12 * ch + o;   // always < 384
            ob[((size_t)gy * IMG + gx) * 4] = acc[o];
        }
    }
}

extern "C" void kernel_launch(void* const* d_in, const int* in_sizes, int n_in,
                              void* d_out, int out_size)
{
    (void)in_sizes; (void)n_in; (void)out_size;
    const float* x = (const float*)d_in[0];
    float* y = (float*)d_out;

    cudaFuncSetAttribute(gauss13_kernel,
                         cudaFuncAttributeMaxDynamicSharedMemorySize, SMEM_BYTES);

    dim3 grid(IMG / W_OUT /* 8 */, IMG / TILE_H /* 12 */, 32 * 2);
    dim3 block(128, 2);
    gauss13_kernel<<<grid, block, SMEM_BYTES>>>(x, y);
}

// round 9
// speedup vs baseline: 1.5398x; 1.0900x over previous
#include <cuda_runtime.h>
#include <cuda_fp16.h>

#define IMG      384
#define W_OUT    48          // 8 * 48 = 384 exact
#define LCOLS    60          // 48 + 6+6 halo
#define TILE_H   32          // output rows per block
#define ROWS_PT  16          // rows per vertical slice
#define S_PIX    60          // 4*60 ≡ 16 (mod 32) -> half-warp conflict-free
#define SMEM_BYTES (TILE_H * S_PIX * 16)   // 30720 B -> 3 blocks/SM

// Normalized 1D gaussian, sigma=2, ws=13
__device__ constexpr float GW[13] = {
    0.0022181959f, 0.0087731350f, 0.0270231560f, 0.0648251852f,
    0.1211093910f, 0.1762131227f, 0.1996756275f, 0.1762131227f,
    0.1211093910f, 0.0648251852f, 0.0270231560f, 0.0087731350f,
    0.0022181959f };

__device__ __forceinline__ float4 f4z() { return make_float4(0.f, 0.f, 0.f, 0.f); }

union H2U { __half2 h; unsigned u; };

// pack float4 -> 2x half2 (2x cvt.rn.f16x2.f32)
__device__ __forceinline__ uint2 pack_h4(float4 v) {
    H2U a, b;
    a.h = __floats2half2_rn(v.x, v.y);
    b.h = __floats2half2_rn(v.z, v.w);
    uint2 r; r.x = a.u; r.y = b.u;
    return r;
}

__global__ __launch_bounds__(256, 3)
void gauss13_kernel(const float* __restrict__ in, float* __restrict__ out)
{
    extern __shared__ uint2 sV[];   // [TILE_H][S_PIX][2 cq] of half4 (8 B)

    const int z  = blockIdx.z;
    const int n  = z >> 1;
    const int p  = z & 1;            // channel half (ch 0-7 / 8-15)
    const int x0 = blockIdx.x * W_OUT;
    const int y0 = blockIdx.y * TILE_H;

    const float4* __restrict__ ibase =
        reinterpret_cast<const float4*>(in) + (size_t)n * (IMG * IMG * 4) + p * 2;
    float4* __restrict__ obase =
        reinterpret_cast<float4*>(out) + (size_t)n * (IMG * IMG * 4) + p * 2;

    // ---------------- vertical pass: fp16 ring + HFMA2 taps -> smem fp16 ----------------
    {
        const int tx  = threadIdx.x;      // 0..127
        const int col = tx >> 1;          // 0..63; only 0..59 active
        const int cq  = tx & 1;
        if (col < LCOLS) {
            const int gw  = x0 - 6 + col;
            const bool wok = ((unsigned)gw < (unsigned)IMG);
            const int r0  = y0 + (int)threadIdx.y * ROWS_PT - 6;
            const float4* cb = ibase + cq;

            uint2 win[13];                 // packed half4 per row
            #pragma unroll
            for (int i = 0; i < 12; ++i) {
                int h = r0 + i;
                win[i] = pack_h4((wok && (unsigned)h < (unsigned)IMG)
                       ? __ldg(cb + ((size_t)h * IMG + gw) * 4) : f4z());
            }
            #pragma unroll
            for (int r = 0; r < ROWS_PT; ++r) {
                int h = r0 + 12 + r;
                win[(r + 12) % 13] = pack_h4((wok && (unsigned)h < (unsigned)IMG)
                       ? __ldg(cb + ((size_t)h * IMG + gw) * 4) : f4z());
                H2U a01, a23;
                a01.h = __float2half2_rn(0.f);
                a23.h = __float2half2_rn(0.f);
                #pragma unroll
                for (int k = 0; k < 13; ++k) {
                    const uint2 w = win[(r + k) % 13];
                    const __half2 wk2 = __float2half2_rn(GW[k]);   // folded const
                    H2U v0, v1; v0.u = w.x; v1.u = w.y;
                    a01.h = __hfma2(wk2, v0.h, a01.h);
                    a23.h = __hfma2(wk2, v1.h, a23.h);
                }
                uint2 pk; pk.x = a01.u; pk.y = a23.u;
                sV[((threadIdx.y * ROWS_PT + r) * S_PIX + col) * 2 + cq] = pk;
            }
        }
    }
    __syncthreads();

    // ---------------- horizontal pass (smem fp16 -> f32 accum -> global) ---------------
    {
        const int tid  = (int)threadIdx.y * 128 + (int)threadIdx.x;  // 0..255
        const int cq   = tid & 1;
        const int seg  = (tid >> 1) & 3;   // output col = seg + 4*i
        const int hrow = tid >> 3;         // 0..31

        float4 acc[12];
        #pragma unroll
        for (int i = 0; i < 12; ++i) acc[i] = f4z();

        const uint2* rowp = sV + (hrow * S_PIX) * 2 + cq;

        #pragma unroll
        for (int c = 0; c < 57; ++c) {     // c in [4i, 4i+12] for i=0..11
            uint2 pk = rowp[(seg + c) * 2];
            H2U u0, u1; u0.u = pk.x; u1.u = pk.y;
            float2 f01 = __half22float2(u0.h);
            float2 f23 = __half22float2(u1.h);
            #pragma unroll
            for (int i = 0; i < 12; ++i) {
                const int k = c - 4 * i;
                if (k >= 0 && k < 13) {     // compile-time pruned
                    const float wk = GW[k]; // literal -> FFMA-imm
                    acc[i].x = fmaf(wk, f01.x, acc[i].x);
                    acc[i].y = fmaf(wk, f01.y, acc[i].y);
                    acc[i].z = fmaf(wk, f23.x, acc[i].z);
                    acc[i].w = fmaf(wk, f23.y, acc[i].w);
                }
            }
        }

        const int gy = y0 + hrow;
        float4* ob = obase + cq;
        #pragma unroll
        for (int i = 0; i < 12; ++i) {
            const int gx = x0 + seg + 4 * i;   // always < 384
            ob[((size_t)gy * IMG + gx) * 4] = acc[i];
        }
    }
}

extern "C" void kernel_launch(void* const* d_in, const int* in_sizes, int n_in,
                              void* d_out, int out_size)
{
    (void)in_sizes; (void)n_in; (void)out_size;
    const float* x = (const float*)d_in[0];
    float* y = (float*)d_out;

    cudaFuncSetAttribute(gauss13_kernel,
                         cudaFuncAttributeMaxDynamicSharedMemorySize, SMEM_BYTES);

    dim3 grid(IMG / W_OUT /* 8 */, IMG / TILE_H /* 12 */, 32 * 2);
    dim3 block(128, 2);
    gauss13_kernel<<<grid, block, SMEM_BYTES>>>(x, y);
}

// round 10
// speedup vs baseline: 1.5591x; 1.0125x over previous
#include <cuda_runtime.h>
#include <cuda_fp16.h>

#define IMG      384
#define W_OUT    48          // 8 * 48 = 384 exact
#define LCOLS    60          // 48 + 6+6 halo
#define TILE_H   16          // output rows per block
#define ROW_U2   (LCOLS * 4) // uint2 (half4) per smem row = 240 -> 1920 B
#define SMEM_BYTES (TILE_H * ROW_U2 * 8)   // 30720 B -> 3 blocks/SM

// Normalized 1D gaussian, sigma=2, ws=13 (literals -> FFMA-imm form)
__device__ constexpr float GW[13] = {
    0.0022181959f, 0.0087731350f, 0.0270231560f, 0.0648251852f,
    0.1211093910f, 0.1762131227f, 0.1996756275f, 0.1762131227f,
    0.1211093910f, 0.0648251852f, 0.0270231560f, 0.0087731350f,
    0.0022181959f };

__device__ __forceinline__ float4 f4z() { return make_float4(0.f, 0.f, 0.f, 0.f); }

union H2U { __half2 h; unsigned u; };

__global__ __launch_bounds__(256, 3)
void gauss13_kernel(const float* __restrict__ in, float* __restrict__ out)
{
    // smem: [TILE_H rows][60 pixels][4 quads] of half4 (8 B). Full 16-ch pixel = 32 B.
    extern __shared__ uint2 sV[];

    const int n  = blockIdx.z;           // batch (full 16 channels per block)
    const int x0 = blockIdx.x * W_OUT;
    const int y0 = blockIdx.y * TILE_H;
    const int tid = threadIdx.x;

    const float4* __restrict__ ibase =
        reinterpret_cast<const float4*>(in) + (size_t)n * (IMG * IMG * 4);
    float4* __restrict__ obase =
        reinterpret_cast<float4*>(out) + (size_t)n * (IMG * IMG * 4);

    // ---------------- vertical pass (global -> smem fp16), register ring ----------------
    // thread = (col 0..59, q 0..3); warp lanes = 8 consecutive pixels x 4 quads
    //  -> every LDG warp instruction reads 512 contiguous bytes (4 lines, 4 wavefronts).
    {
        const int q   = tid & 3;
        const int col = tid >> 2;          // 0..63; only 0..59 active
        if (col < LCOLS) {
            const int gw  = x0 - 6 + col;
            const bool wok = ((unsigned)gw < (unsigned)IMG);
            const int r0  = y0 - 6;
            const float4* cb = ibase + q;
            uint2* sp = sV + col * 4 + q;

            float4 win[13];
            #pragma unroll
            for (int i = 0; i < 12; ++i) {
                int h = r0 + i;
                win[i] = (wok && (unsigned)h < (unsigned)IMG)
                       ? __ldg(cb + ((size_t)h * IMG + gw) * 4) : f4z();
            }
            #pragma unroll
            for (int r = 0; r < TILE_H; ++r) {
                int h = r0 + 12 + r;
                win[(r + 12) % 13] = (wok && (unsigned)h < (unsigned)IMG)
                       ? __ldg(cb + ((size_t)h * IMG + gw) * 4) : f4z();
                float4 a = f4z();
                #pragma unroll
                for (int k = 0; k < 13; ++k) {
                    const float4 v = win[(r + k) % 13];
                    const float wk = GW[k];      // literal -> FFMA-imm
                    a.x = fmaf(wk, v.x, a.x);
                    a.y = fmaf(wk, v.y, a.y);
                    a.z = fmaf(wk, v.z, a.z);
                    a.w = fmaf(wk, v.w, a.w);
                }
                H2U u0, u1;
                u0.h = __floats2half2_rn(a.x, a.y);
                u1.h = __floats2half2_rn(a.z, a.w);
                uint2 pk; pk.x = u0.u; pk.y = u1.u;
                sp[r * ROW_U2] = pk;     // 16-lane phase writes 128 B contiguous: conflict-free
            }
        }
    }
    __syncthreads();

    // ---------------- horizontal pass (smem fp16 -> global f32) -------------------------
    // thread = (q, seg, row): 4*4*16 = 256. Outputs {seg + 4i} -> warp stores cover
    // 4 consecutive FULL pixels x 2 rows = 4 lines per STG instruction.
    {
        const int q   = tid & 3;
        const int seg = (tid >> 2) & 3;
        const int row = tid >> 4;          // 0..15

        float4 acc[12];
        #pragma unroll
        for (int i = 0; i < 12; ++i) acc[i] = f4z();

        const uint2* rowp = sV + row * ROW_U2 + q;

        #pragma unroll
        for (int c = 0; c < 57; ++c) {     // c in [4i, 4i+12] for i = 0..11
            uint2 pk = rowp[(seg + c) * 4];
            H2U u0, u1; u0.u = pk.x; u1.u = pk.y;
            float2 f01 = __half22float2(u0.h);
            float2 f23 = __half22float2(u1.h);
            #pragma unroll
            for (int i = 0; i < 12; ++i) {
                const int k = c - 4 * i;
                if (k >= 0 && k < 13) {     // compile-time pruned
                    const float wk = GW[k]; // literal -> FFMA-imm
                    acc[i].x = fmaf(wk, f01.x, acc[i].x);
                    acc[i].y = fmaf(wk, f01.y, acc[i].y);
                    acc[i].z = fmaf(wk, f23.x, acc[i].z);
                    acc[i].w = fmaf(wk, f23.y, acc[i].w);
                }
            }
        }

        const int gy = y0 + row;
        float4* ob = obase + q;
        #pragma unroll
        for (int i = 0; i < 12; ++i) {
            const int gx = x0 + seg + 4 * i;   // always < 384
            ob[((size_t)gy * IMG + gx) * 4] = acc[i];
        }
    }
}

extern "C" void kernel_launch(void* const* d_in, const int* in_sizes, int n_in,
                              void* d_out, int out_size)
{
    (void)in_sizes; (void)n_in; (void)out_size;
    const float* x = (const float*)d_in[0];
    float* y = (float*)d_out;

    cudaFuncSetAttribute(gauss13_kernel,
                         cudaFuncAttributeMaxDynamicSharedMemorySize, SMEM_BYTES);

    dim3 grid(IMG / W_OUT /* 8 */, IMG / TILE_H /* 24 */, 32);
    dim3 block(256);
    gauss13_kernel<<<grid, block, SMEM_BYTES>>>(x, y);
}

// round 11
// speedup vs baseline: 1.7080x; 1.0955x over previous
#include <cuda_runtime.h>
#include <cuda_fp16.h>

#define IMG      384
#define W_OUT    48          // 8 * 48 = 384 exact
#define LCOLS    60          // 48 + 6+6 halo
#define TILE_H   16          // output rows per block
#define ROW_U2   (LCOLS * 4) // uint2 (half4) per smem row = 240 -> 1920 B
#define SMEM_BYTES (TILE_H * ROW_U2 * 8)   // 30720 B -> 4 blocks/SM (122.9 KB)

// Normalized 1D gaussian, sigma=2, ws=13 (literals -> FFMA-imm / HFMA2-imm form)
__device__ constexpr float GW[13] = {
    0.0022181959f, 0.0087731350f, 0.0270231560f, 0.0648251852f,
    0.1211093910f, 0.1762131227f, 0.1996756275f, 0.1762131227f,
    0.1211093910f, 0.0648251852f, 0.0270231560f, 0.0087731350f,
    0.0022181959f };

__device__ __forceinline__ float4 f4z() { return make_float4(0.f, 0.f, 0.f, 0.f); }

union H2U { __half2 h; unsigned u; };

// pack float4 -> 2x half2
__device__ __forceinline__ uint2 pack_h4(float4 v) {
    H2U a, b;
    a.h = __floats2half2_rn(v.x, v.y);
    b.h = __floats2half2_rn(v.z, v.w);
    uint2 r; r.x = a.u; r.y = b.u;
    return r;
}

__global__ __launch_bounds__(256, 4)
void gauss13_kernel(const float* __restrict__ in, float* __restrict__ out)
{
    // smem: [TILE_H rows][60 pixels][4 quads] of half4 (8 B). Full 16-ch pixel = 32 B.
    extern __shared__ uint2 sV[];

    const int n  = blockIdx.z;           // batch (full 16 channels per block)
    const int x0 = blockIdx.x * W_OUT;
    const int y0 = blockIdx.y * TILE_H;
    const int tid = threadIdx.x;

    const float4* __restrict__ ibase =
        reinterpret_cast<const float4*>(in) + (size_t)n * (IMG * IMG * 4);
    float4* __restrict__ obase =
        reinterpret_cast<float4*>(out) + (size_t)n * (IMG * IMG * 4);

    // ------------- vertical pass: packed fp16 ring + HFMA2 -> smem fp16 -------------
    // thread = (col 0..59, q 0..3); warp lanes = 8 consecutive pixels x 4 quads
    {
        const int q   = tid & 3;
        const int col = tid >> 2;          // 0..63; only 0..59 active
        if (col < LCOLS) {
            const int gw  = x0 - 6 + col;
            const bool wok = ((unsigned)gw < (unsigned)IMG);
            const int r0  = y0 - 6;
            const float4* cb = ibase + q;
            uint2* sp = sV + col * 4 + q;

            uint2 win[13];                 // packed half4 ring (26 regs)
            #pragma unroll
            for (int i = 0; i < 12; ++i) {
                int h = r0 + i;
                win[i] = pack_h4((wok && (unsigned)h < (unsigned)IMG)
                       ? __ldg(cb + ((size_t)h * IMG + gw) * 4) : f4z());
            }
            #pragma unroll
            for (int r = 0; r < TILE_H; ++r) {
                int h = r0 + 12 + r;
                win[(r + 12) % 13] = pack_h4((wok && (unsigned)h < (unsigned)IMG)
                       ? __ldg(cb + ((size_t)h * IMG + gw) * 4) : f4z());
                H2U a01, a23;
                a01.h = __float2half2_rn(0.f);
                a23.h = __float2half2_rn(0.f);
                #pragma unroll
                for (int k = 0; k < 13; ++k) {
                    const uint2 w = win[(r + k) % 13];
                    const __half2 wk2 = __float2half2_rn(GW[k]);  // folded const
                    H2U v0, v1; v0.u = w.x; v1.u = w.y;
                    a01.h = __hfma2(wk2, v0.h, a01.h);
                    a23.h = __hfma2(wk2, v1.h, a23.h);
                }
                uint2 pk; pk.x = a01.u; pk.y = a23.u;
                sp[r * ROW_U2] = pk;       // 16-lane phase = 128 B contiguous: conflict-free
            }
        }
    }
    __syncthreads();

    // ------------- horizontal pass (smem fp16 -> f32 accum -> global) ----------------
    // thread = (q, seg, row): warp stores 4 consecutive full pixels x 2 rows.
    {
        const int q   = tid & 3;
        const int seg = (tid >> 2) & 3;
        const int row = tid >> 4;          // 0..15

        float4 acc[12];
        #pragma unroll
        for (int i = 0; i < 12; ++i) acc[i] = f4z();

        const uint2* rowp = sV + row * ROW_U2 + q;

        #pragma unroll
        for (int c = 0; c < 57; ++c) {     // c in [4i, 4i+12] for i = 0..11
            uint2 pk = rowp[(seg + c) * 4];
            H2U u0, u1; u0.u = pk.x; u1.u = pk.y;
            float2 f01 = __half22float2(u0.h);
            float2 f23 = __half22float2(u1.h);
            #pragma unroll
            for (int i = 0; i < 12; ++i) {
                const int k = c - 4 * i;
                if (k >= 0 && k < 13) {     // compile-time pruned
                    const float wk = GW[k]; // literal -> FFMA-imm
                    acc[i].x = fmaf(wk, f01.x, acc[i].x);
                    acc[i].y = fmaf(wk, f01.y, acc[i].y);
                    acc[i].z = fmaf(wk, f23.x, acc[i].z);
                    acc[i].w = fmaf(wk, f23.y, acc[i].w);
                }
            }
        }

        const int gy = y0 + row;
        float4* ob = obase + q;
        #pragma unroll
        for (int i = 0; i < 12; ++i) {
            const int gx = x0 + seg + 4 * i;   // always < 384
            ob[((size_t)gy * IMG + gx) * 4] = acc[i];
        }
    }
}

extern "C" void kernel_launch(void* const* d_in, const int* in_sizes, int n_in,
                              void* d_out, int out_size)
{
    (void)in_sizes; (void)n_in; (void)out_size;
    const float* x = (const float*)d_in[0];
    float* y = (float*)d_out;

    cudaFuncSetAttribute(gauss13_kernel,
                         cudaFuncAttributeMaxDynamicSharedMemorySize, SMEM_BYTES);

    dim3 grid(IMG / W_OUT /* 8 */, IMG / TILE_H /* 24 */, 32);
    dim3 block(256);
    gauss13_kernel<<<grid, block, SMEM_BYTES>>>(x, y);
}